// round 2
// baseline (speedup 1.0000x reference)
#include <cuda_runtime.h>

#define NATOMS 256
#define PDIM 2
#define LDIM 9
#define FDIM 64
#define ROWLEN (PDIM*LDIM*FDIM)                 // 1152 floats per (a,b)
#define GK (NATOMS*ROWLEN)                      // 294912 = K of the big GEMM
#define NROWS_TOTAL (NATOMS*NATOMS*PDIM*LDIM)   // 1,179,648 rows of 64

// ---------------- scratch (static device globals; no runtime alloc) ----------
__device__ float g_T[NATOMS * GK];        // 302 MB: T = x @ M
__device__ float g_M[PDIM * FDIM * FDIM]; // M_p = Wq_p Wk_p^T
__device__ float g_dot[NATOMS * NATOMS];
__device__ float g_w[NATOMS * NATOMS];
__device__ int   g_idx[NATOMS * NATOMS];
__device__ float g_wval[NATOMS * NATOMS];
__device__ int   g_nnz[NATOMS];

// ---------------- K0: zero accumulators (must re-run every graph replay) -----
__global__ void k0_zero() {
    int i = blockIdx.x * blockDim.x + threadIdx.x;
    if (i < NATOMS * NATOMS) g_dot[i] = 0.0f;
    if (i < NATOMS) g_nnz[i] = 0;
}

// ---------------- K1: M[p][e][f] = sum_g Wq[p][e][g] * Wk[p][f][g] -----------
__global__ void k1_M(const float* __restrict__ Wq, const float* __restrict__ Wk) {
    int id = blockIdx.x * blockDim.x + threadIdx.x;   // 8192 outputs
    if (id >= PDIM * FDIM * FDIM) return;
    int p = id >> 12;
    int e = (id >> 6) & 63;
    int f = id & 63;
    const float* q = Wq + (p << 12) + (e << 6);
    const float* k = Wk + (p << 12) + (f << 6);
    float s = 0.0f;
#pragma unroll 16
    for (int g = 0; g < 64; g++) s += q[g] * k[g];
    g_M[id] = s;
}

// ---------------- K2: T[r][f] = sum_e x[r][e] * M[p(r)][e][f] ----------------
// One thread owns one row (64-wide), 64 fp32 accumulators, M broadcast from smem.
__global__ __launch_bounds__(256, 2) void k2_T(const float* __restrict__ x) {
    __shared__ float xS[256 * 65];          // padded: conflict-free row reads
    __shared__ float MS[PDIM * FDIM * FDIM];
    int t = threadIdx.x;
    int r0 = blockIdx.x * 256;
    const float* gx = x + (size_t)r0 * 64;

    // stage x tile (256 rows x 64) coalesced, scalar STS into padded layout
#pragma unroll
    for (int i = 0; i < 16; i++) {
        float4 v = *(const float4*)(gx + i * 1024 + t * 4);
        int row = i * 16 + (t >> 4);
        int e   = (t & 15) * 4;
        float* d = xS + row * 65 + e;
        d[0] = v.x; d[1] = v.y; d[2] = v.z; d[3] = v.w;
    }
#pragma unroll
    for (int i = 0; i < 8; i++)
        *(float4*)(MS + i * 1024 + t * 4) = *(const float4*)(g_M + i * 1024 + t * 4);
    __syncthreads();

    int r = r0 + t;
    int p = (r / LDIM) & 1;                 // r = ((a*256+b)*2+p)*9+l
    const float4* Mp = (const float4*)(MS + (p << 12));
    const float* xrow = xS + t * 65;

    float acc[64];
#pragma unroll
    for (int f = 0; f < 64; f++) acc[f] = 0.0f;

#pragma unroll 4
    for (int e = 0; e < 64; e++) {
        float xv = xrow[e];
#pragma unroll
        for (int f4 = 0; f4 < 16; f4++) {
            float4 m = Mp[e * 16 + f4];
            acc[f4 * 4 + 0] += xv * m.x;
            acc[f4 * 4 + 1] += xv * m.y;
            acc[f4 * 4 + 2] += xv * m.z;
            acc[f4 * 4 + 3] += xv * m.w;
        }
    }
    float4* dst = (float4*)(g_T + (size_t)r * 64);
#pragma unroll
    for (int i = 0; i < 16; i++)
        dst[i] = make_float4(acc[4*i], acc[4*i+1], acc[4*i+2], acc[4*i+3]);
}

// ---------------- K3: dot = T * x^T  (256x256, K=294912), split-K SIMT sgemm -
// 128x128 tile, BK=8, 256 threads, 8x8 microtile (4+4 split), atomicAdd epilogue.
#define K3_KCHUNK 4096
__global__ __launch_bounds__(256, 2) void k3_dot(const float* __restrict__ x) {
    __shared__ float As[2][8][128];
    __shared__ float Bs[2][8][128];
    int t = threadIdx.x;
    int m0 = blockIdx.x * 128;
    int n0 = blockIdx.y * 128;
    size_t kb = (size_t)blockIdx.z * K3_KCHUNK;

    int ldrow = t >> 1;
    int ldk   = (t & 1) * 4;
    const float* Ag = g_T + (size_t)(m0 + ldrow) * GK + kb + ldk;
    const float* Bg = x   + (size_t)(n0 + ldrow) * GK + kb + ldk;

    // stage 0
    {
        float4 va = *(const float4*)Ag;
        float4 vb = *(const float4*)Bg;
        As[0][ldk+0][ldrow] = va.x; As[0][ldk+1][ldrow] = va.y;
        As[0][ldk+2][ldrow] = va.z; As[0][ldk+3][ldrow] = va.w;
        Bs[0][ldk+0][ldrow] = vb.x; Bs[0][ldk+1][ldrow] = vb.y;
        Bs[0][ldk+2][ldrow] = vb.z; Bs[0][ldk+3][ldrow] = vb.w;
    }
    __syncthreads();

    int ty = t >> 4, tx = t & 15;
    float acc[8][8];
#pragma unroll
    for (int i = 0; i < 8; i++)
#pragma unroll
        for (int j = 0; j < 8; j++) acc[i][j] = 0.0f;

    int buf = 0;
    const int NSTAGE = K3_KCHUNK / 8;   // 512
    for (int kt = 1; kt <= NSTAGE; kt++) {
        float4 na, nb;
        if (kt < NSTAGE) {
            na = *(const float4*)(Ag + (size_t)kt * 8);
            nb = *(const float4*)(Bg + (size_t)kt * 8);
        }
#pragma unroll
        for (int k = 0; k < 8; k++) {
            float4 a0 = *(const float4*)&As[buf][k][ty * 4];
            float4 a1 = *(const float4*)&As[buf][k][64 + ty * 4];
            float4 b0 = *(const float4*)&Bs[buf][k][tx * 4];
            float4 b1 = *(const float4*)&Bs[buf][k][64 + tx * 4];
            float av[8] = {a0.x,a0.y,a0.z,a0.w,a1.x,a1.y,a1.z,a1.w};
            float bv[8] = {b0.x,b0.y,b0.z,b0.w,b1.x,b1.y,b1.z,b1.w};
#pragma unroll
            for (int i = 0; i < 8; i++)
#pragma unroll
                for (int j = 0; j < 8; j++)
                    acc[i][j] += av[i] * bv[j];
        }
        if (kt < NSTAGE) {
            int nbuf = buf ^ 1;
            As[nbuf][ldk+0][ldrow] = na.x; As[nbuf][ldk+1][ldrow] = na.y;
            As[nbuf][ldk+2][ldrow] = na.z; As[nbuf][ldk+3][ldrow] = na.w;
            Bs[nbuf][ldk+0][ldrow] = nb.x; Bs[nbuf][ldk+1][ldrow] = nb.y;
            Bs[nbuf][ldk+2][ldrow] = nb.z; Bs[nbuf][ldk+3][ldrow] = nb.w;
            __syncthreads();
            buf = nbuf;
        }
    }

#pragma unroll
    for (int i = 0; i < 8; i++) {
        int row = m0 + ((i < 4) ? (ty * 4 + i) : (64 + ty * 4 + i - 4));
#pragma unroll
        for (int j = 0; j < 8; j++) {
            int col = n0 + ((j < 4) ? (tx * 4 + j) : (64 + tx * 4 + j - 4));
            atomicAdd(&g_dot[row * NATOMS + col], acc[i][j]);
        }
    }
}

// ---------------- K4: softmax over axis a (per column c) ---------------------
__global__ void k4_softmax() {
    int c = blockIdx.x, t = threadIdx.x;
    __shared__ float red[256];
    float v = g_dot[t * NATOMS + c];
    red[t] = v; __syncthreads();
    for (int s = 128; s > 0; s >>= 1) {
        if (t < s) red[t] = fmaxf(red[t], red[t + s]);
        __syncthreads();
    }
    float mx = red[0]; __syncthreads();
    float e = expf(v - mx);
    red[t] = e; __syncthreads();
    for (int s = 128; s > 0; s >>= 1) {
        if (t < s) red[t] += red[t + s];
        __syncthreads();
    }
    g_w[t * NATOMS + c] = e / red[0];
}

// ---------------- K5: compact nonzero weights per output row a (ordered) -----
__global__ void k5_compact() {
    int a = blockIdx.x, t = threadIdx.x;
    float wv = g_w[a * NATOMS + t];
    bool nz = (wv != 0.0f);
    unsigned m = __ballot_sync(0xffffffffu, nz);
    int lane = t & 31, warp = t >> 5;
    int pre = __popc(m & ((1u << lane) - 1u));
    __shared__ int wcnt[8], woff[8];
    if (lane == 0) wcnt[warp] = __popc(m);
    __syncthreads();
    if (t == 0) {
        int s = 0;
        for (int i = 0; i < 8; i++) { woff[i] = s; s += wcnt[i]; }
        g_nnz[a] = s;
    }
    __syncthreads();
    if (nz) {
        int pos = woff[warp] + pre;
        g_idx[a * NATOMS + pos]  = t;
        g_wval[a * NATOMS + pos] = wv;
    }
}

// ---------------- K6: out[a,row,f] = sum_e (sum_j w_j x[b_j,row,e]) Wv[p][e][f]
__global__ __launch_bounds__(256, 2) void k6_out(const float* __restrict__ x,
                                                 const float* __restrict__ Wv,
                                                 float* __restrict__ out) {
    __shared__ float yS[256 * 65];
    __shared__ float WS[PDIM * FDIM * FDIM];
    __shared__ float wlist[NATOMS];
    __shared__ int   blist[NATOMS];
    __shared__ int   s_nnz;
    int t = threadIdx.x;
    int a = blockIdx.y;
    int r0 = blockIdx.x * 256;          // row index within a's (c,p,l) space [0,4608)

    if (t == 0) s_nnz = g_nnz[a];
#pragma unroll
    for (int i = 0; i < 8; i++)
        *(float4*)(WS + i * 1024 + t * 4) = *(const float4*)(Wv + i * 1024 + t * 4);
    __syncthreads();
    int nnz = s_nnz;
    if (t < nnz) { blist[t] = g_idx[a * NATOMS + t]; wlist[t] = g_wval[a * NATOMS + t]; }
    __syncthreads();

    // phase 1: y[row][e] = sum_j w_j * x[b_j, r0+row, e]   (coalesced float4)
    int rowt = t >> 4;
    int e4   = (t & 15) * 4;
#pragma unroll 2
    for (int i = 0; i < 16; i++) {
        int row = i * 16 + rowt;
        size_t off = (size_t)(r0 + row) * 64 + e4;
        float ax = 0.f, ay = 0.f, az = 0.f, aw = 0.f;
        for (int j = 0; j < nnz; j++) {
            const float4 v = *(const float4*)(x + (size_t)blist[j] * GK + off);
            float w = wlist[j];
            ax += w * v.x; ay += w * v.y; az += w * v.z; aw += w * v.w;
        }
        float* d = yS + row * 65 + e4;
        d[0] = ax; d[1] = ay; d[2] = az; d[3] = aw;
    }
    __syncthreads();

    // phase 2: thread owns one row; out[row][f] = sum_e y[row][e]*Wv[p][e][f]
    int rg = r0 + t;
    int p = (rg / LDIM) & 1;            // rg = (c*2+p)*9+l
    const float4* Wp = (const float4*)(WS + (p << 12));
    const float* yrow = yS + t * 65;

    float acc[64];
#pragma unroll
    for (int f = 0; f < 64; f++) acc[f] = 0.0f;

#pragma unroll 4
    for (int e = 0; e < 64; e++) {
        float yv = yrow[e];
#pragma unroll
        for (int f4 = 0; f4 < 16; f4++) {
            float4 m = Wp[e * 16 + f4];
            acc[f4 * 4 + 0] += yv * m.x;
            acc[f4 * 4 + 1] += yv * m.y;
            acc[f4 * 4 + 2] += yv * m.z;
            acc[f4 * 4 + 3] += yv * m.w;
        }
    }
    float4* dst = (float4*)(out + (size_t)a * GK + (size_t)rg * 64);
#pragma unroll
    for (int i = 0; i < 16; i++)
        dst[i] = make_float4(acc[4*i], acc[4*i+1], acc[4*i+2], acc[4*i+3]);
}

// ---------------- launch ------------------------------------------------------
extern "C" void kernel_launch(void* const* d_in, const int* in_sizes, int n_in,
                              void* d_out, int out_size) {
    const float* x  = (const float*)d_in[0];
    const float* Wq = (const float*)d_in[1];
    const float* Wk = (const float*)d_in[2];
    const float* Wv = (const float*)d_in[3];
    float* out = (float*)d_out;
    (void)in_sizes; (void)n_in; (void)out_size;

    k0_zero<<<(NATOMS * NATOMS + 255) / 256, 256>>>();
    k1_M<<<(PDIM * FDIM * FDIM + 255) / 256, 256>>>(Wq, Wk);
    k2_T<<<NROWS_TOTAL / 256, 256>>>(x);
    {
        dim3 grid(2, 2, GK / K3_KCHUNK);   // 2 x 2 x 72 = 288 blocks
        k3_dot<<<grid, 256>>>(x);
    }
    k4_softmax<<<NATOMS, NATOMS>>>();
    k5_compact<<<NATOMS, NATOMS>>>();
    {
        dim3 grid((NATOMS * PDIM * LDIM) / 256, NATOMS);   // 18 x 256
        k6_out<<<grid, 256>>>(x, Wv, out);
    }
}

// round 3
// speedup vs baseline: 1.0218x; 1.0218x over previous
#include <cuda_runtime.h>
#include <cuda_bf16.h>

#define NATOMS 256
#define PDIM 2
#define LDIM 9
#define FDIM 64
#define ROWLEN (PDIM*LDIM*FDIM)                 // 1152 floats per (a,b)
#define GK (NATOMS*ROWLEN)                      // 294912 = K of the big GEMM
#define NROWS_TOTAL (NATOMS*NATOMS*PDIM*LDIM)   // 1,179,648 rows of 64

// ---------------- scratch (static device globals; no runtime alloc) ----------
__device__ float          g_T [NATOMS * GK];      // 302 MB fp32 T = x @ M
__device__ __nv_bfloat16  g_Th[NATOMS * GK];      // 151 MB bf16(T)
__device__ __nv_bfloat16  g_xh[NATOMS * GK];      // 151 MB bf16(x)
__device__ float g_M[PDIM * FDIM * FDIM];         // M_p = Wq_p Wk_p^T
__device__ float g_dotb[NATOMS * NATOMS];         // bf16-GEMM logits (approx)
__device__ float g_dot [NATOMS * NATOMS];         // exact logits (-inf elsewhere)
__device__ float g_w[NATOMS * NATOMS];
__device__ int   g_idx[NATOMS * NATOMS];
__device__ float g_wval[NATOMS * NATOMS];
__device__ int   g_nnz[NATOMS];
__device__ int   g_cand[NATOMS * NATOMS];         // packed (a<<8)|c
__device__ int   g_ncand;

// ---------------- K0: init accumulators (re-run every replay) ---------------
__global__ void k0_zero() {
    int i = blockIdx.x * blockDim.x + threadIdx.x;
    if (i < NATOMS * NATOMS) {
        g_dotb[i] = 0.0f;
        g_dot[i]  = __int_as_float(0xff800000);   // -inf
    }
    if (i < NATOMS) g_nnz[i] = 0;
    if (i == 0) g_ncand = 0;
}

// ---------------- K1: M[p][e][f] = sum_g Wq[p][e][g] * Wk[p][f][g] ----------
__global__ void k1_M(const float* __restrict__ Wq, const float* __restrict__ Wk) {
    int id = blockIdx.x * blockDim.x + threadIdx.x;
    if (id >= PDIM * FDIM * FDIM) return;
    int p = id >> 12;
    int e = (id >> 6) & 63;
    int f = id & 63;
    const float* q = Wq + (p << 12) + (e << 6);
    const float* k = Wk + (p << 12) + (f << 6);
    float s = 0.0f;
#pragma unroll 16
    for (int g = 0; g < 64; g++) s += q[g] * k[g];
    g_M[id] = s;
}

static __device__ __forceinline__ unsigned pack_bf2(float lo, float hi) {
    __nv_bfloat162 h2 = __floats2bfloat162_rn(lo, hi);
    return *reinterpret_cast<unsigned*>(&h2);
}

// ---------------- K2: T = x*M (fp32) + emit bf16 Th and bf16 xh --------------
__global__ __launch_bounds__(256, 2) void k2_T(const float* __restrict__ x) {
    __shared__ float xS[256 * 65];
    __shared__ float MS[PDIM * FDIM * FDIM];
    int t = threadIdx.x;
    int r0 = blockIdx.x * 256;
    const float* gx = x + (size_t)r0 * 64;

#pragma unroll
    for (int i = 0; i < 16; i++) {
        float4 v = *(const float4*)(gx + i * 1024 + t * 4);
        int row = i * 16 + (t >> 4);
        int e   = (t & 15) * 4;
        float* d = xS + row * 65 + e;
        d[0] = v.x; d[1] = v.y; d[2] = v.z; d[3] = v.w;
    }
#pragma unroll
    for (int i = 0; i < 8; i++)
        *(float4*)(MS + i * 1024 + t * 4) = *(const float4*)(g_M + i * 1024 + t * 4);
    __syncthreads();

    int r = r0 + t;
    int p = (r / LDIM) & 1;
    const float4* Mp = (const float4*)(MS + (p << 12));
    const float* xrow = xS + t * 65;

    float acc[64];
#pragma unroll
    for (int f = 0; f < 64; f++) acc[f] = 0.0f;

#pragma unroll 4
    for (int e = 0; e < 64; e++) {
        float xv = xrow[e];
#pragma unroll
        for (int f4 = 0; f4 < 16; f4++) {
            float4 m = Mp[e * 16 + f4];
            acc[f4 * 4 + 0] += xv * m.x;
            acc[f4 * 4 + 1] += xv * m.y;
            acc[f4 * 4 + 2] += xv * m.z;
            acc[f4 * 4 + 3] += xv * m.w;
        }
    }
    float4* dst = (float4*)(g_T + (size_t)r * 64);
#pragma unroll
    for (int i = 0; i < 16; i++)
        dst[i] = make_float4(acc[4*i], acc[4*i+1], acc[4*i+2], acc[4*i+3]);

    unsigned* thd = (unsigned*)(g_Th + (size_t)r * 64);
    unsigned* xhd = (unsigned*)(g_xh + (size_t)r * 64);
#pragma unroll
    for (int i = 0; i < 32; i++) {
        thd[i] = pack_bf2(acc[2*i], acc[2*i+1]);
        xhd[i] = pack_bf2(xrow[2*i], xrow[2*i+1]);
    }
}

// ---------------- K3t: dotb = Th * xh^T via mma.sync bf16 (fp32 accum) -------
#define K3_KCHUNK 4096
#define K3T_STAGES 4
#define APITCH 24                         // bf16 per smem row (48B, bank-safe)
#define STAGE_BYTES (128 * APITCH * 2)    // 6144

static __device__ __forceinline__ void cpa16(unsigned sdst, const void* gsrc) {
    asm volatile("cp.async.cg.shared.global [%0], [%1], 16;\n" :: "r"(sdst), "l"(gsrc));
}
static __device__ __forceinline__ void ldsm_x4(unsigned r[4], unsigned addr) {
    asm volatile("ldmatrix.sync.aligned.m8n8.x4.shared.b16 {%0,%1,%2,%3}, [%4];\n"
        : "=r"(r[0]), "=r"(r[1]), "=r"(r[2]), "=r"(r[3]) : "r"(addr));
}
static __device__ __forceinline__ void mma_bf16(float d[4], const unsigned a[4],
                                                const unsigned b0, const unsigned b1) {
    asm volatile("mma.sync.aligned.m16n8k16.row.col.f32.bf16.bf16.f32 "
        "{%0,%1,%2,%3},{%4,%5,%6,%7},{%8,%9},{%0,%1,%2,%3};\n"
        : "+f"(d[0]), "+f"(d[1]), "+f"(d[2]), "+f"(d[3])
        : "r"(a[0]), "r"(a[1]), "r"(a[2]), "r"(a[3]), "r"(b0), "r"(b1));
}

__global__ __launch_bounds__(256, 2) void k3t_dot() {
    __shared__ __nv_bfloat16 As[K3T_STAGES][128 * APITCH];
    __shared__ __nv_bfloat16 Bs[K3T_STAGES][128 * APITCH];
    const int t = threadIdx.x;
    const int m0 = blockIdx.x * 128, n0 = blockIdx.y * 128;
    const size_t kb = (size_t)blockIdx.z * K3_KCHUNK;

    const unsigned uA = (unsigned)__cvta_generic_to_shared(&As[0][0]);
    const unsigned uB = (unsigned)__cvta_generic_to_shared(&Bs[0][0]);

    const int row = t >> 1, half = t & 1;
    const __nv_bfloat16* ga = g_Th + (size_t)(m0 + row) * GK + kb + half * 8;
    const __nv_bfloat16* gb = g_xh + (size_t)(n0 + row) * GK + kb + half * 8;
    const unsigned sdA = uA + (row * APITCH + half * 8) * 2;
    const unsigned sdB = uB + (row * APITCH + half * 8) * 2;

    const int NS = K3_KCHUNK / 16;   // 256 k-steps

    // prologue: fill first 3 stages
#pragma unroll
    for (int s = 0; s < K3T_STAGES - 1; s++) {
        cpa16(sdA + s * STAGE_BYTES, ga + (size_t)s * 16);
        cpa16(sdB + s * STAGE_BYTES, gb + (size_t)s * 16);
        asm volatile("cp.async.commit_group;\n");
    }

    const int warp = t >> 5, lane = t & 31;
    const int wm = warp >> 2, wn = warp & 3;       // 2 x 4 warp grid: 64m x 32n each
    const unsigned aBase = uA + ((wm * 64 + (lane & 15)) * APITCH + (lane >> 4) * 8) * 2;
    const unsigned bBase = uB + ((wn * 32 + (lane & 15)) * APITCH + (lane >> 4) * 8) * 2;

    float acc[4][4][4] = {};

    for (int ks = 0; ks < NS; ks++) {
        asm volatile("cp.async.wait_group %0;\n" :: "n"(K3T_STAGES - 2));
        __syncthreads();
        const int buf = ks & (K3T_STAGES - 1);

        unsigned afr[4][4], bfr[2][4];
#pragma unroll
        for (int i = 0; i < 4; i++)
            ldsm_x4(afr[i], aBase + buf * STAGE_BYTES + i * 16 * APITCH * 2);
#pragma unroll
        for (int j = 0; j < 2; j++)
            ldsm_x4(bfr[j], bBase + buf * STAGE_BYTES + j * 16 * APITCH * 2);

#pragma unroll
        for (int i = 0; i < 4; i++)
#pragma unroll
            for (int j = 0; j < 4; j++) {
                unsigned b0 = bfr[j >> 1][(j & 1)];
                unsigned b1 = bfr[j >> 1][(j & 1) + 2];
                mma_bf16(acc[i][j], afr[i], b0, b1);
            }

        const int pf = ks + K3T_STAGES - 1;
        if (pf < NS) {
            const int pbuf = pf & (K3T_STAGES - 1);
            cpa16(sdA + pbuf * STAGE_BYTES, ga + (size_t)pf * 16);
            cpa16(sdB + pbuf * STAGE_BYTES, gb + (size_t)pf * 16);
        }
        asm volatile("cp.async.commit_group;\n");
    }
    asm volatile("cp.async.wait_group 0;\n");

    const int lr = lane >> 2, lc = (lane & 3) * 2;
#pragma unroll
    for (int i = 0; i < 4; i++)
#pragma unroll
        for (int j = 0; j < 4; j++) {
            int r = m0 + wm * 64 + i * 16 + lr;
            int c = n0 + wn * 32 + j * 8 + lc;
            atomicAdd(&g_dotb[r * NATOMS + c],           acc[i][j][0]);
            atomicAdd(&g_dotb[r * NATOMS + c + 1],       acc[i][j][1]);
            atomicAdd(&g_dotb[(r + 8) * NATOMS + c],     acc[i][j][2]);
            atomicAdd(&g_dotb[(r + 8) * NATOMS + c + 1], acc[i][j][3]);
        }
}

// ---------------- K4b: per column, find bf16 max; emit candidates -----------
#define CAND_MARGIN 30.0f
__global__ void k4b_cand() {
    int c = blockIdx.x, t = threadIdx.x;
    __shared__ float red[256];
    __shared__ int wcnt[8], woff[8], sbase;
    float v = g_dotb[t * NATOMS + c];
    red[t] = v; __syncthreads();
    for (int s = 128; s > 0; s >>= 1) {
        if (t < s) red[t] = fmaxf(red[t], red[t + s]);
        __syncthreads();
    }
    float thr = red[0] - CAND_MARGIN;
    bool cand = (v >= thr);
    unsigned m = __ballot_sync(0xffffffffu, cand);
    int lane = t & 31, warp = t >> 5;
    int pre = __popc(m & ((1u << lane) - 1u));
    if (lane == 0) wcnt[warp] = __popc(m);
    __syncthreads();
    if (t == 0) {
        int s = 0;
        for (int i = 0; i < 8; i++) { woff[i] = s; s += wcnt[i]; }
        sbase = atomicAdd(&g_ncand, s);
    }
    __syncthreads();
    if (cand) g_cand[sbase + woff[warp] + pre] = (t << 8) | c;   // a = t
}

// ---------------- K5x: exact fp32 logits for candidates ----------------------
__global__ __launch_bounds__(256) void k5x_exact(const float* __restrict__ x) {
    __shared__ float red[256];
    int t = threadIdx.x;
    int nc = g_ncand;
    for (int ci = blockIdx.x; ci < nc; ci += gridDim.x) {
        int pk = g_cand[ci];
        int a = pk >> 8, c = pk & 255;
        const float4* A = (const float4*)(g_T + (size_t)a * GK);
        const float4* B = (const float4*)(x   + (size_t)c * GK);
        float s = 0.0f;
        for (int k = t; k < GK / 4; k += 256) {
            float4 va = A[k], vb = B[k];
            s += va.x * vb.x + va.y * vb.y + va.z * vb.z + va.w * vb.w;
        }
        red[t] = s; __syncthreads();
        for (int st = 128; st > 0; st >>= 1) {
            if (t < st) red[t] += red[t + st];
            __syncthreads();
        }
        if (t == 0) g_dot[a * NATOMS + c] = red[0];
        __syncthreads();
    }
}

// ---------------- K4: softmax over axis a (per column c); -inf -> 0 ----------
__global__ void k4_softmax() {
    int c = blockIdx.x, t = threadIdx.x;
    __shared__ float red[256];
    float v = g_dot[t * NATOMS + c];
    red[t] = v; __syncthreads();
    for (int s = 128; s > 0; s >>= 1) {
        if (t < s) red[t] = fmaxf(red[t], red[t + s]);
        __syncthreads();
    }
    float mx = red[0]; __syncthreads();
    float e = expf(v - mx);
    red[t] = e; __syncthreads();
    for (int s = 128; s > 0; s >>= 1) {
        if (t < s) red[t] += red[t + s];
        __syncthreads();
    }
    g_w[t * NATOMS + c] = e / red[0];
}

// ---------------- K5: compact nonzero weights per output row a ---------------
__global__ void k5_compact() {
    int a = blockIdx.x, t = threadIdx.x;
    float wv = g_w[a * NATOMS + t];
    bool nz = (wv != 0.0f);
    unsigned m = __ballot_sync(0xffffffffu, nz);
    int lane = t & 31, warp = t >> 5;
    int pre = __popc(m & ((1u << lane) - 1u));
    __shared__ int wcnt[8], woff[8];
    if (lane == 0) wcnt[warp] = __popc(m);
    __syncthreads();
    if (t == 0) {
        int s = 0;
        for (int i = 0; i < 8; i++) { woff[i] = s; s += wcnt[i]; }
        g_nnz[a] = s;
    }
    __syncthreads();
    if (nz) {
        int pos = woff[warp] + pre;
        g_idx[a * NATOMS + pos]  = t;
        g_wval[a * NATOMS + pos] = wv;
    }
}

// ---------------- K6: out[a,row,f] = (sum_j w_j x[b_j,row,:]) * Wv[p] --------
__global__ __launch_bounds__(256, 2) void k6_out(const float* __restrict__ x,
                                                 const float* __restrict__ Wv,
                                                 float* __restrict__ out) {
    __shared__ float yS[256 * 65];
    __shared__ float WS[PDIM * FDIM * FDIM];
    __shared__ float wlist[NATOMS + 4];
    __shared__ int   blist[NATOMS + 4];
    __shared__ int   s_nnz;
    int t = threadIdx.x;
    int a = blockIdx.y;
    int r0 = blockIdx.x * 256;

    if (t == 0) s_nnz = g_nnz[a];
#pragma unroll
    for (int i = 0; i < 8; i++)
        *(float4*)(WS + i * 1024 + t * 4) = *(const float4*)(Wv + i * 1024 + t * 4);
    __syncthreads();
    int nnz = s_nnz;
    int nnzp = (nnz + 3) & ~3;
    if (t < nnzp) {
        if (t < nnz) { blist[t] = g_idx[a * NATOMS + t]; wlist[t] = g_wval[a * NATOMS + t]; }
        else         { blist[t] = 0;                     wlist[t] = 0.0f; }
    }
    __syncthreads();

    // phase 1: y[row][e] = sum_j w_j * x[b_j, r0+row, e]  (4-wide unrolled gather)
    int rowt = t >> 4;
    int e4   = (t & 15) * 4;
#pragma unroll 2
    for (int i = 0; i < 16; i++) {
        int row = i * 16 + rowt;
        size_t off = (size_t)(r0 + row) * 64 + e4;
        float ax = 0.f, ay = 0.f, az = 0.f, aw = 0.f;
        for (int j = 0; j < nnzp; j += 4) {
            const float4 v0 = *(const float4*)(x + (size_t)blist[j+0] * GK + off);
            const float4 v1 = *(const float4*)(x + (size_t)blist[j+1] * GK + off);
            const float4 v2 = *(const float4*)(x + (size_t)blist[j+2] * GK + off);
            const float4 v3 = *(const float4*)(x + (size_t)blist[j+3] * GK + off);
            float w0 = wlist[j+0], w1 = wlist[j+1], w2 = wlist[j+2], w3 = wlist[j+3];
            ax += w0*v0.x + w1*v1.x + w2*v2.x + w3*v3.x;
            ay += w0*v0.y + w1*v1.y + w2*v2.y + w3*v3.y;
            az += w0*v0.z + w1*v1.z + w2*v2.z + w3*v3.z;
            aw += w0*v0.w + w1*v1.w + w2*v2.w + w3*v3.w;
        }
        float* d = yS + row * 65 + e4;
        d[0] = ax; d[1] = ay; d[2] = az; d[3] = aw;
    }
    __syncthreads();

    // phase 2: out[row][f] = sum_e y[row][e]*Wv[p][e][f]
    int rg = r0 + t;
    int p = (rg / LDIM) & 1;
    const float4* Wp = (const float4*)(WS + (p << 12));
    const float* yrow = yS + t * 65;

    float acc[64];
#pragma unroll
    for (int f = 0; f < 64; f++) acc[f] = 0.0f;

#pragma unroll 4
    for (int e = 0; e < 64; e++) {
        float yv = yrow[e];
#pragma unroll
        for (int f4 = 0; f4 < 16; f4++) {
            float4 m = Wp[e * 16 + f4];
            acc[f4 * 4 + 0] += yv * m.x;
            acc[f4 * 4 + 1] += yv * m.y;
            acc[f4 * 4 + 2] += yv * m.z;
            acc[f4 * 4 + 3] += yv * m.w;
        }
    }
    float4* dst = (float4*)(out + (size_t)a * GK + (size_t)rg * 64);
#pragma unroll
    for (int i = 0; i < 16; i++)
        dst[i] = make_float4(acc[4*i], acc[4*i+1], acc[4*i+2], acc[4*i+3]);
}

// ---------------- launch ------------------------------------------------------
extern "C" void kernel_launch(void* const* d_in, const int* in_sizes, int n_in,
                              void* d_out, int out_size) {
    const float* x  = (const float*)d_in[0];
    const float* Wq = (const float*)d_in[1];
    const float* Wk = (const float*)d_in[2];
    const float* Wv = (const float*)d_in[3];
    float* out = (float*)d_out;
    (void)in_sizes; (void)n_in; (void)out_size;

    k0_zero<<<(NATOMS * NATOMS + 255) / 256, 256>>>();
    k1_M<<<(PDIM * FDIM * FDIM + 255) / 256, 256>>>(Wq, Wk);
    k2_T<<<NROWS_TOTAL / 256, 256>>>(x);
    {
        dim3 grid(2, 2, GK / K3_KCHUNK);   // 2 x 2 x 72 = 288 blocks
        k3t_dot<<<grid, 256>>>();
    }
    k4b_cand<<<NATOMS, NATOMS>>>();
    k5x_exact<<<512, 256>>>(x);
    k4_softmax<<<NATOMS, NATOMS>>>();
    k5_compact<<<NATOMS, NATOMS>>>();
    {
        dim3 grid((NATOMS * PDIM * LDIM) / 256, NATOMS);   // 18 x 256
        k6_out<<<grid, 256>>>(x, Wv, out);
    }
}

// round 4
// speedup vs baseline: 1.1616x; 1.1368x over previous
#include <cuda_runtime.h>
#include <cuda_bf16.h>

#define NATOMS 256
#define PDIM 2
#define LDIM 9
#define FDIM 64
#define ROWLEN (PDIM*LDIM*FDIM)                 // 1152 floats per (a,b)
#define GK (NATOMS*ROWLEN)                      // 294912 = K of the big GEMM
#define NROWS_TOTAL (NATOMS*NATOMS*PDIM*LDIM)   // 1,179,648 rows of 64

// ---------------- scratch (static device globals; no runtime alloc) ----------
__device__ __nv_bfloat16  g_Thi[NATOMS * GK];     // bf16 hi(T)
__device__ __nv_bfloat16  g_Tlo[NATOMS * GK];     // bf16 lo(T)
__device__ __nv_bfloat16  g_xhi[NATOMS * GK];     // bf16 hi(x)
__device__ __nv_bfloat16  g_xlo[NATOMS * GK];     // bf16 lo(x)
__device__ float g_M[PDIM * FDIM * FDIM];         // M_p = Wq_p Wk_p^T
__device__ float g_dotb[NATOMS * NATOMS];         // split-GEMM logits (accurate)
__device__ float g_w[NATOMS * NATOMS];
__device__ int   g_idx[NATOMS * NATOMS];
__device__ float g_wval[NATOMS * NATOMS];
__device__ int   g_nnz[NATOMS];
__device__ int   g_ccol[NATOMS];                  // columns needing exact recompute
__device__ int   g_calist[NATOMS * 8];            // a-lists per such column
__device__ int   g_cak[NATOMS];
__device__ int   g_nccols;

// ---------------- K0: init accumulators (re-run every replay) ---------------
__global__ void k0_zero() {
    int i = blockIdx.x * blockDim.x + threadIdx.x;
    if (i < NATOMS * NATOMS) g_dotb[i] = 0.0f;
    if (i < NATOMS) g_nnz[i] = 0;
    if (i == 0) g_nccols = 0;
}

// ---------------- K1: M[p][e][f] = sum_g Wq[p][e][g] * Wk[p][f][g] ----------
__global__ void k1_M(const float* __restrict__ Wq, const float* __restrict__ Wk) {
    int id = blockIdx.x * blockDim.x + threadIdx.x;
    if (id >= PDIM * FDIM * FDIM) return;
    int p = id >> 12;
    int e = (id >> 6) & 63;
    int f = id & 63;
    const float* q = Wq + (p << 12) + (e << 6);
    const float* k = Wk + (p << 12) + (f << 6);
    float s = 0.0f;
#pragma unroll 16
    for (int g = 0; g < 64; g++) s += q[g] * k[g];
    g_M[id] = s;
}

static __device__ __forceinline__ unsigned pack_hi2(float a, float b) {
    __nv_bfloat162 h2 = __floats2bfloat162_rn(a, b);
    return *reinterpret_cast<unsigned*>(&h2);
}
static __device__ __forceinline__ unsigned pack_lo2(float a, float b) {
    float ra = a - __bfloat162float(__float2bfloat16_rn(a));
    float rb = b - __bfloat162float(__float2bfloat16_rn(b));
    __nv_bfloat162 h2 = __floats2bfloat162_rn(ra, rb);
    return *reinterpret_cast<unsigned*>(&h2);
}

// ---------------- K2: T = x*M (fp32), emit hi/lo bf16 of T and x -------------
__global__ __launch_bounds__(256, 2) void k2_T(const float* __restrict__ x) {
    __shared__ float xS[256 * 65];
    __shared__ float MS[PDIM * FDIM * FDIM];
    int t = threadIdx.x;
    int r0 = blockIdx.x * 256;
    const float* gx = x + (size_t)r0 * 64;

#pragma unroll
    for (int i = 0; i < 16; i++) {
        float4 v = *(const float4*)(gx + i * 1024 + t * 4);
        int row = i * 16 + (t >> 4);
        int e   = (t & 15) * 4;
        float* d = xS + row * 65 + e;
        d[0] = v.x; d[1] = v.y; d[2] = v.z; d[3] = v.w;
    }
#pragma unroll
    for (int i = 0; i < 8; i++)
        *(float4*)(MS + i * 1024 + t * 4) = *(const float4*)(g_M + i * 1024 + t * 4);
    __syncthreads();

    int r = r0 + t;
    int p = (r / LDIM) & 1;
    const float4* Mp = (const float4*)(MS + (p << 12));
    const float* xrow = xS + t * 65;

    float acc[64];
#pragma unroll
    for (int f = 0; f < 64; f++) acc[f] = 0.0f;

#pragma unroll 4
    for (int e = 0; e < 64; e++) {
        float xv = xrow[e];
#pragma unroll
        for (int f4 = 0; f4 < 16; f4++) {
            float4 m = Mp[e * 16 + f4];
            acc[f4 * 4 + 0] += xv * m.x;
            acc[f4 * 4 + 1] += xv * m.y;
            acc[f4 * 4 + 2] += xv * m.z;
            acc[f4 * 4 + 3] += xv * m.w;
        }
    }

    uint4* thh = (uint4*)(g_Thi + (size_t)r * 64);
    uint4* thl = (uint4*)(g_Tlo + (size_t)r * 64);
    uint4* xhh = (uint4*)(g_xhi + (size_t)r * 64);
    uint4* xhl = (uint4*)(g_xlo + (size_t)r * 64);
#pragma unroll
    for (int i = 0; i < 8; i++) {
        const float* a = acc + i * 8;
        const float* xr = xrow + i * 8;
        uint4 vh, vl, wh, wl;
        vh.x = pack_hi2(a[0], a[1]); vh.y = pack_hi2(a[2], a[3]);
        vh.z = pack_hi2(a[4], a[5]); vh.w = pack_hi2(a[6], a[7]);
        vl.x = pack_lo2(a[0], a[1]); vl.y = pack_lo2(a[2], a[3]);
        vl.z = pack_lo2(a[4], a[5]); vl.w = pack_lo2(a[6], a[7]);
        wh.x = pack_hi2(xr[0], xr[1]); wh.y = pack_hi2(xr[2], xr[3]);
        wh.z = pack_hi2(xr[4], xr[5]); wh.w = pack_hi2(xr[6], xr[7]);
        wl.x = pack_lo2(xr[0], xr[1]); wl.y = pack_lo2(xr[2], xr[3]);
        wl.z = pack_lo2(xr[4], xr[5]); wl.w = pack_lo2(xr[6], xr[7]);
        thh[i] = vh; thl[i] = vl; xhh[i] = wh; xhl[i] = wl;
    }
}

// ---------------- K3s: dotb = Thi*xhi^T + Thi*xlo^T + Tlo*xhi^T (mma bf16) ---
#define K3_KCHUNK 4096
#define PITCH 16
#define STAGE_BYTES (128 * PITCH * 2)   // 4096

static __device__ __forceinline__ void cpa16(unsigned sdst, const void* gsrc) {
    asm volatile("cp.async.cg.shared.global [%0], [%1], 16;\n" :: "r"(sdst), "l"(gsrc));
}
static __device__ __forceinline__ void ldsm_x4(unsigned r[4], unsigned addr) {
    asm volatile("ldmatrix.sync.aligned.m8n8.x4.shared.b16 {%0,%1,%2,%3}, [%4];\n"
        : "=r"(r[0]), "=r"(r[1]), "=r"(r[2]), "=r"(r[3]) : "r"(addr));
}
static __device__ __forceinline__ void mma_bf16(float d[4], const unsigned a[4],
                                                const unsigned b0, const unsigned b1) {
    asm volatile("mma.sync.aligned.m16n8k16.row.col.f32.bf16.bf16.f32 "
        "{%0,%1,%2,%3},{%4,%5,%6,%7},{%8,%9},{%0,%1,%2,%3};\n"
        : "+f"(d[0]), "+f"(d[1]), "+f"(d[2]), "+f"(d[3])
        : "r"(a[0]), "r"(a[1]), "r"(a[2]), "r"(a[3]), "r"(b0), "r"(b1));
}

__global__ __launch_bounds__(256) void k3s_dot() {
    __shared__ __nv_bfloat16 Ah[3][128 * PITCH];
    __shared__ __nv_bfloat16 Al[3][128 * PITCH];
    __shared__ __nv_bfloat16 Bh[3][128 * PITCH];
    __shared__ __nv_bfloat16 Bl[3][128 * PITCH];
    const int t = threadIdx.x;
    const int m0 = blockIdx.x * 128, n0 = blockIdx.y * 128;
    const size_t kb = (size_t)blockIdx.z * K3_KCHUNK;

    const unsigned uAh = (unsigned)__cvta_generic_to_shared(&Ah[0][0]);
    const unsigned uAl = (unsigned)__cvta_generic_to_shared(&Al[0][0]);
    const unsigned uBh = (unsigned)__cvta_generic_to_shared(&Bh[0][0]);
    const unsigned uBl = (unsigned)__cvta_generic_to_shared(&Bl[0][0]);

    const int row = t >> 1, half = t & 1;
    const size_t goff = (size_t)row * GK + kb + half * 8;
    const __nv_bfloat16* gah = g_Thi + (size_t)m0 * GK + goff;
    const __nv_bfloat16* gal = g_Tlo + (size_t)m0 * GK + goff;
    const __nv_bfloat16* gbh = g_xhi + (size_t)n0 * GK + goff;
    const __nv_bfloat16* gbl = g_xlo + (size_t)n0 * GK + goff;
    const unsigned soff = (row * PITCH + half * 8) * 2;

    const int NS = K3_KCHUNK / 16;   // 256 k-steps

#pragma unroll
    for (int s = 0; s < 2; s++) {
        cpa16(uAh + soff + s * STAGE_BYTES, gah + (size_t)s * 16);
        cpa16(uAl + soff + s * STAGE_BYTES, gal + (size_t)s * 16);
        cpa16(uBh + soff + s * STAGE_BYTES, gbh + (size_t)s * 16);
        cpa16(uBl + soff + s * STAGE_BYTES, gbl + (size_t)s * 16);
        asm volatile("cp.async.commit_group;\n");
    }

    const int warp = t >> 5, lane = t & 31;
    const int wm = warp >> 2, wn = warp & 3;
    const unsigned aoff = ((wm * 64 + (lane & 15)) * PITCH + (lane >> 4) * 8) * 2;
    const unsigned boff = ((wn * 32 + (lane & 15)) * PITCH + (lane >> 4) * 8) * 2;

    float acc[4][4][4] = {};

    int buf = 0, pbuf = 2;
    for (int ks = 0; ks < NS; ks++) {
        asm volatile("cp.async.wait_group %0;\n" :: "n"(1));
        __syncthreads();

        unsigned ah[4][4], al[4][4], bh[2][4], bl[2][4];
#pragma unroll
        for (int i = 0; i < 4; i++) {
            ldsm_x4(ah[i], uAh + aoff + buf * STAGE_BYTES + i * 16 * PITCH * 2);
            ldsm_x4(al[i], uAl + aoff + buf * STAGE_BYTES + i * 16 * PITCH * 2);
        }
#pragma unroll
        for (int j = 0; j < 2; j++) {
            ldsm_x4(bh[j], uBh + boff + buf * STAGE_BYTES + j * 16 * PITCH * 2);
            ldsm_x4(bl[j], uBl + boff + buf * STAGE_BYTES + j * 16 * PITCH * 2);
        }

#pragma unroll
        for (int i = 0; i < 4; i++)
#pragma unroll
            for (int j = 0; j < 4; j++) {
                unsigned bh0 = bh[j >> 1][(j & 1)],     bh1 = bh[j >> 1][(j & 1) + 2];
                unsigned bl0 = bl[j >> 1][(j & 1)],     bl1 = bl[j >> 1][(j & 1) + 2];
                mma_bf16(acc[i][j], ah[i], bh0, bh1);
                mma_bf16(acc[i][j], ah[i], bl0, bl1);
                mma_bf16(acc[i][j], al[i], bh0, bh1);
            }

        const int pf = ks + 2;
        if (pf < NS) {
            cpa16(uAh + soff + pbuf * STAGE_BYTES, gah + (size_t)pf * 16);
            cpa16(uAl + soff + pbuf * STAGE_BYTES, gal + (size_t)pf * 16);
            cpa16(uBh + soff + pbuf * STAGE_BYTES, gbh + (size_t)pf * 16);
            cpa16(uBl + soff + pbuf * STAGE_BYTES, gbl + (size_t)pf * 16);
        }
        asm volatile("cp.async.commit_group;\n");
        buf = (buf == 2) ? 0 : buf + 1;
        pbuf = (pbuf == 2) ? 0 : pbuf + 1;
    }
    asm volatile("cp.async.wait_group 0;\n");

    const int lr = lane >> 2, lc = (lane & 3) * 2;
#pragma unroll
    for (int i = 0; i < 4; i++)
#pragma unroll
        for (int j = 0; j < 4; j++) {
            int r = m0 + wm * 64 + i * 16 + lr;
            int c = n0 + wn * 32 + j * 8 + lc;
            atomicAdd(&g_dotb[r * NATOMS + c],           acc[i][j][0]);
            atomicAdd(&g_dotb[r * NATOMS + c + 1],       acc[i][j][1]);
            atomicAdd(&g_dotb[(r + 8) * NATOMS + c],     acc[i][j][2]);
            atomicAdd(&g_dotb[(r + 8) * NATOMS + c + 1], acc[i][j][3]);
        }
}

// ---------------- K4b: find columns with >=2 entries within gap 14 -----------
#define CLOSE_MARGIN 14.0f
__global__ void k4b_close() {
    int c = blockIdx.x, t = threadIdx.x;
    __shared__ float red[256];
    __shared__ int cnt, pos;
    if (t == 0) { cnt = 0; pos = 0; }
    float v = g_dotb[t * NATOMS + c];
    red[t] = v; __syncthreads();
    for (int s = 128; s > 0; s >>= 1) {
        if (t < s) red[t] = fmaxf(red[t], red[t + s]);
        __syncthreads();
    }
    float mx = red[0];
    bool cand = (v >= mx - CLOSE_MARGIN);
    if (cand) atomicAdd(&cnt, 1);
    __syncthreads();
    if (cnt >= 2) {
        if (t == 0) { int s = atomicAdd(&g_nccols, 1); g_ccol[s] = c; }
        if (cand) {
            int p = atomicAdd(&pos, 1);
            if (p < 8) { g_calist[c * 8 + p] = t; g_dotb[t * NATOMS + c] = 0.0f; }
        }
        __syncthreads();
        if (t == 0) g_cak[c] = (cnt < 8) ? cnt : 8;
    }
}

// ---------------- K5x: exact fp32 logits for close columns, from x & M -------
// block (chunk, s): rows [chunk*256, +256); dot(a,c) += xa_row . (M_p . xc_row)
__global__ __launch_bounds__(256) void k5x_exact(const float* __restrict__ x) {
    __shared__ float Msh[2 * 4096];
    __shared__ float red[256];
    int s = blockIdx.y;
    if (s >= g_nccols) return;
    int t = threadIdx.x;
    int c = g_ccol[s];
    int ka = g_cak[c];

    for (int i = t; i < 8192 / 4; i += 256)
        ((float4*)Msh)[i] = ((const float4*)g_M)[i];
    __syncthreads();

    int row = blockIdx.x * 256 + t;        // [0, 4608)
    int p = (row / LDIM) & 1;
    const float* Mp = Msh + (p << 12);

    float xc[64];
    {
        const float4* xcp = (const float4*)(x + (size_t)c * GK + (size_t)row * 64);
#pragma unroll
        for (int i = 0; i < 16; i++) {
            float4 v = xcp[i];
            xc[4*i] = v.x; xc[4*i+1] = v.y; xc[4*i+2] = v.z; xc[4*i+3] = v.w;
        }
    }
    float z[64];
#pragma unroll 4
    for (int e = 0; e < 64; e++) {
        const float4* Mr = (const float4*)(Mp + e * 64);
        float sm = 0.0f;
#pragma unroll
        for (int f4 = 0; f4 < 16; f4++) {
            float4 m = Mr[f4];
            sm += m.x * xc[4*f4] + m.y * xc[4*f4+1] + m.z * xc[4*f4+2] + m.w * xc[4*f4+3];
        }
        z[e] = sm;
    }

    for (int j = 0; j < ka; j++) {
        int a = g_calist[c * 8 + j];
        const float4* xap = (const float4*)(x + (size_t)a * GK + (size_t)row * 64);
        float sd = 0.0f;
#pragma unroll
        for (int i = 0; i < 16; i++) {
            float4 v = xap[i];
            sd += v.x * z[4*i] + v.y * z[4*i+1] + v.z * z[4*i+2] + v.w * z[4*i+3];
        }
        red[t] = sd; __syncthreads();
        for (int st = 128; st > 0; st >>= 1) {
            if (t < st) red[t] += red[t + st];
            __syncthreads();
        }
        if (t == 0) atomicAdd(&g_dotb[a * NATOMS + c], red[0]);
        __syncthreads();
    }
}

// ---------------- K4: softmax over axis a (per column c) ---------------------
__global__ void k4_softmax() {
    int c = blockIdx.x, t = threadIdx.x;
    __shared__ float red[256];
    float v = g_dotb[t * NATOMS + c];
    red[t] = v; __syncthreads();
    for (int s = 128; s > 0; s >>= 1) {
        if (t < s) red[t] = fmaxf(red[t], red[t + s]);
        __syncthreads();
    }
    float mx = red[0]; __syncthreads();
    float e = expf(v - mx);
    red[t] = e; __syncthreads();
    for (int s = 128; s > 0; s >>= 1) {
        if (t < s) red[t] += red[t + s];
        __syncthreads();
    }
    g_w[t * NATOMS + c] = e / red[0];
}

// ---------------- K5: compact significant weights per output row a -----------
__global__ void k5_compact() {
    int a = blockIdx.x, t = threadIdx.x;
    float wv = g_w[a * NATOMS + t];
    bool nz = (wv > 1e-7f);
    unsigned m = __ballot_sync(0xffffffffu, nz);
    int lane = t & 31, warp = t >> 5;
    int pre = __popc(m & ((1u << lane) - 1u));
    __shared__ int wcnt[8], woff[8];
    if (lane == 0) wcnt[warp] = __popc(m);
    __syncthreads();
    if (t == 0) {
        int s = 0;
        for (int i = 0; i < 8; i++) { woff[i] = s; s += wcnt[i]; }
        g_nnz[a] = s;
    }
    __syncthreads();
    if (nz) {
        int pos = woff[warp] + pre;
        g_idx[a * NATOMS + pos]  = t;
        g_wval[a * NATOMS + pos] = wv;
    }
}

// ---------------- K6: out[a,row,f] = (sum_j w_j x[b_j,row,:]) * Wv[p] --------
__global__ __launch_bounds__(256, 2) void k6_out(const float* __restrict__ x,
                                                 const float* __restrict__ Wv,
                                                 float* __restrict__ out) {
    __shared__ float yS[256 * 65];
    __shared__ float WS[PDIM * FDIM * FDIM];
    __shared__ float wlist[NATOMS];
    __shared__ int   blist[NATOMS];
    __shared__ int   s_nnz;
    int t = threadIdx.x;
    int a = blockIdx.y;
    int r0 = blockIdx.x * 256;

    if (t == 0) s_nnz = g_nnz[a];
    __syncthreads();
    int nnz = s_nnz;

    if (nnz == 0) {   // entire output slab is zero
        float4* dst = (float4*)(out + (size_t)a * GK + (size_t)(r0 + t) * 64);
        float4 z = make_float4(0.f, 0.f, 0.f, 0.f);
#pragma unroll
        for (int i = 0; i < 16; i++) dst[i] = z;
        return;
    }

#pragma unroll
    for (int i = 0; i < 8; i++)
        *(float4*)(WS + i * 1024 + t * 4) = *(const float4*)(Wv + i * 1024 + t * 4);
    if (t < nnz) { blist[t] = g_idx[a * NATOMS + t]; wlist[t] = g_wval[a * NATOMS + t]; }
    __syncthreads();

    // phase 1: y[row][e] = sum_j w_j * x[b_j, r0+row, e]   (exact-length, 2-wide)
    int rowt = t >> 4;
    int e4   = (t & 15) * 4;
#pragma unroll 2
    for (int i = 0; i < 16; i++) {
        int row = i * 16 + rowt;
        size_t off = (size_t)(r0 + row) * 64 + e4;
        float ax = 0.f, ay = 0.f, az = 0.f, aw = 0.f;
        int j = 0;
        for (; j + 1 < nnz; j += 2) {
            const float4 v0 = *(const float4*)(x + (size_t)blist[j]   * GK + off);
            const float4 v1 = *(const float4*)(x + (size_t)blist[j+1] * GK + off);
            float w0 = wlist[j], w1 = wlist[j+1];
            ax += w0*v0.x + w1*v1.x; ay += w0*v0.y + w1*v1.y;
            az += w0*v0.z + w1*v1.z; aw += w0*v0.w + w1*v1.w;
        }
        if (j < nnz) {
            const float4 v0 = *(const float4*)(x + (size_t)blist[j] * GK + off);
            float w0 = wlist[j];
            ax += w0*v0.x; ay += w0*v0.y; az += w0*v0.z; aw += w0*v0.w;
        }
        float* d = yS + row * 65 + e4;
        d[0] = ax; d[1] = ay; d[2] = az; d[3] = aw;
    }
    __syncthreads();

    // phase 2: out[row][f] = sum_e y[row][e]*Wv[p][e][f]
    int rg = r0 + t;
    int p = (rg / LDIM) & 1;
    const float4* Wp = (const float4*)(WS + (p << 12));
    const float* yrow = yS + t * 65;

    float acc[64];
#pragma unroll
    for (int f = 0; f < 64; f++) acc[f] = 0.0f;

#pragma unroll 4
    for (int e = 0; e < 64; e++) {
        float yv = yrow[e];
#pragma unroll
        for (int f4 = 0; f4 < 16; f4++) {
            float4 m = Wp[e * 16 + f4];
            acc[f4 * 4 + 0] += yv * m.x;
            acc[f4 * 4 + 1] += yv * m.y;
            acc[f4 * 4 + 2] += yv * m.z;
            acc[f4 * 4 + 3] += yv * m.w;
        }
    }
    float4* dst = (float4*)(out + (size_t)a * GK + (size_t)rg * 64);
#pragma unroll
    for (int i = 0; i < 16; i++)
        dst[i] = make_float4(acc[4*i], acc[4*i+1], acc[4*i+2], acc[4*i+3]);
}

// ---------------- launch ------------------------------------------------------
extern "C" void kernel_launch(void* const* d_in, const int* in_sizes, int n_in,
                              void* d_out, int out_size) {
    const float* x  = (const float*)d_in[0];
    const float* Wq = (const float*)d_in[1];
    const float* Wk = (const float*)d_in[2];
    const float* Wv = (const float*)d_in[3];
    float* out = (float*)d_out;
    (void)in_sizes; (void)n_in; (void)out_size;

    k0_zero<<<(NATOMS * NATOMS + 255) / 256, 256>>>();
    k1_M<<<(PDIM * FDIM * FDIM + 255) / 256, 256>>>(Wq, Wk);
    k2_T<<<NROWS_TOTAL / 256, 256>>>(x);
    {
        dim3 grid(2, 2, GK / K3_KCHUNK);   // 2 x 2 x 72 = 288 blocks
        k3s_dot<<<grid, 256>>>();
    }
    k4b_close<<<NATOMS, NATOMS>>>();
    {
        dim3 grid(18, NATOMS);             // chunk x (column slot, guarded)
        k5x_exact<<<grid, 256>>>(x);
    }
    k4_softmax<<<NATOMS, NATOMS>>>();
    k5_compact<<<NATOMS, NATOMS>>>();
    {
        dim3 grid((NATOMS * PDIM * LDIM) / 256, NATOMS);   // 18 x 256
        k6_out<<<grid, 256>>>(x, Wv, out);
    }
}